// round 14
// baseline (speedup 1.0000x reference)
#include <cuda_runtime.h>
#include <cuda_bf16.h>
#include <cstdint>

#define BB 8
#define NN 256
#define DD 128
#define HH 8
#define DH 64
#define DQ 32
#define MAXD 5.0f

// ---------------- device scratch (no allocation allowed) ----------------
__device__ float         g_nproj[BB * NN * DH];   // [B,N,64] row-major
__device__ float         g_nprojT[BB * DH * NN];  // [B,64,N] o-major (coalesced)
__device__ float         g_WnT[DD * DH];          // W_node transposed [k][o]
__device__ __nv_bfloat16 g_Wb1[DH * DH];          // folded layer-1 weight [o][k] bf16
__device__ __nv_bfloat16 g_Wb2[DQ * DH];          // W2 [m][o] bf16
__device__ float         g_b1eff[DH];
__device__ float         g_w1c[DH];               // W1[:,96]/MAXD

// ---------------- helpers ----------------
__device__ __forceinline__ uint32_t smem_u32(const void* p) {
    uint32_t a;
    asm("{ .reg .u64 t; cvta.to.shared.u64 t, %1; cvt.u32.u64 %0, t; }" : "=r"(a) : "l"(p));
    return a;
}
#define SWZ128(off) ((off) ^ (((off) >> 3) & 0x70))

#define PACK_BF16X2(res, a, b) \
    asm("cvt.rn.satfinite.bf16x2.f32 %0, %1, %2;" : "=r"(res) : "f"(b), "f"(a))

#define STS128(a, r0, r1, r2, r3) \
    asm volatile("st.shared.v4.b32 [%0], {%1,%2,%3,%4};" :: "r"(a), "r"(r0), "r"(r1), "r"(r2), "r"(r3) : "memory")

__device__ __forceinline__ void ldsm_x4(uint32_t* r, uint32_t addr) {
    asm volatile("ldmatrix.sync.aligned.m8n8.x4.shared.b16 {%0,%1,%2,%3}, [%4];"
                 : "=r"(r[0]), "=r"(r[1]), "=r"(r[2]), "=r"(r[3]) : "r"(addr));
}
__device__ __forceinline__ void ldsm_x2(uint32_t* r, uint32_t addr) {
    asm volatile("ldmatrix.sync.aligned.m8n8.x2.shared.b16 {%0,%1}, [%2];"
                 : "=r"(r[0]), "=r"(r[1]) : "r"(addr));
}
__device__ __forceinline__ void mma16816(float& d0, float& d1, float& d2, float& d3,
                                         uint32_t a0, uint32_t a1, uint32_t a2, uint32_t a3,
                                         uint32_t b0, uint32_t b1) {
    asm volatile("mma.sync.aligned.m16n8k16.row.col.f32.bf16.bf16.f32 "
                 "{%0,%1,%2,%3}, {%4,%5,%6,%7}, {%8,%9}, {%0,%1,%2,%3};"
                 : "+f"(d0), "+f"(d1), "+f"(d2), "+f"(d3)
                 : "r"(a0), "r"(a1), "r"(a2), "r"(a3), "r"(b0), "r"(b1));
}

// ---------------- SMEM layout (dynamic) ----------------
#define SM_BUF   0        // 256 rows x 128B (ef, bf16, swizzled)   (32768)
#define SM_WB1   32768    // 64 x 128B swizzled                      (8192)
#define SM_WB2   40960    // 32 x 128B swizzled                      (4096)
#define SM_W3B   45056    // 8 rows x 80B bf16                       (640)
#define SM_CD    45696    // 256 f                                   (1024)
#define SM_MSK   46720    // 256 f                                   (1024)
#define SM_NI    47744    // 64 f
#define SM_B1    48000    // 64 f
#define SM_W1C   48256    // 64 f
#define SM_B2    48512    // 32 f
#define SM_B3    48640    // 8 f
#define SM_TOTAL 48672

// ---------------------------------------------------------------------------
// prep1: weight folding to bf16 + W_node transpose. grid 224 x 64 threads.
// ---------------------------------------------------------------------------
__global__ void prep1_kernel(const float* __restrict__ Wn,
                             const float* __restrict__ W_edge,
                             const float* __restrict__ b_edge,
                             const float* __restrict__ W1,
                             const float* __restrict__ b1,
                             const float* __restrict__ W2) {
    const int blk = blockIdx.x;
    const int t = threadIdx.x;   // 64 threads
    if (blk < DH) {
        int o = blk, k = t;
        float acc = W1[o * 97 + k];
        #pragma unroll
        for (int m = 0; m < DQ; ++m)
            acc = fmaf(W1[o * 97 + 64 + m], W_edge[m * DD + k], acc);
        g_Wb1[o * DH + k] = __float2bfloat16_rn(acc);
        if (k == 0) {
            float bb = b1[o];
            #pragma unroll
            for (int m = 0; m < DQ; ++m)
                bb = fmaf(W1[o * 97 + 64 + m], b_edge[m], bb);
            g_b1eff[o] = bb;
            g_w1c[o] = W1[o * 97 + 96] * (1.0f / MAXD);
        }
    } else if (blk < DH + DQ) {
        int m = blk - DH;
        g_Wb2[m * DH + t] = __float2bfloat16_rn(W2[m * DH + t]);
    } else {
        int k = blk - (DH + DQ);          // 0..127
        g_WnT[k * DH + t] = Wn[t * DD + k];
    }
}

// ---------------------------------------------------------------------------
// prep2: nproj row; writes row-major + o-major copies.
// ---------------------------------------------------------------------------
__global__ void prep2_kernel(const float* __restrict__ nf,
                             const float* __restrict__ bn) {
    const int row = blockIdx.x;           // b*256 + n
    const int o = threadIdx.x;            // 64 threads
    __shared__ float sx[DD];
    const float* x = nf + (size_t)row * DD;
    sx[o] = x[o];
    sx[o + 64] = x[o + 64];
    __syncthreads();
    float a0 = 0.f, a1 = 0.f, a2 = 0.f, a3 = 0.f;
    #pragma unroll
    for (int k = 0; k < DD; k += 4) {
        a0 = fmaf(g_WnT[(k + 0) * DH + o], sx[k + 0], a0);
        a1 = fmaf(g_WnT[(k + 1) * DH + o], sx[k + 1], a1);
        a2 = fmaf(g_WnT[(k + 2) * DH + o], sx[k + 2], a2);
        a3 = fmaf(g_WnT[(k + 3) * DH + o], sx[k + 3], a3);
    }
    const float v = (a0 + a1) + (a2 + a3) + bn[o];
    g_nproj[row * DH + o] = v;
    const int b = row >> 8, n = row & 255;
    g_nprojT[((size_t)b * DH + o) * NN + n] = v;
}

// ---------------------------------------------------------------------------
// Main: CTA per (b,i). mt-outer pipeline halves register peak -> 3 CTAs/SM.
// ---------------------------------------------------------------------------
__global__ __launch_bounds__(256, 3)
void sparsity_main_kernel(const float* __restrict__ chem,
                          const int* __restrict__ mask,
                          const float* __restrict__ b2,
                          const float* __restrict__ W3,
                          const float* __restrict__ b3,
                          float* __restrict__ out) {
    const int i = blockIdx.x;
    const int b = blockIdx.y;
    const int tid = threadIdx.x;            // == row j
    const int lane = tid & 31;
    const int wid = tid >> 5;

    extern __shared__ char sm[];
    const uint32_t smb = smem_u32(sm);
    float* smf = (float*)sm;

    // ---- cooperative smem fills ----
    for (int idx = tid; idx < DH * DH; idx += 256) {       // Wb1 swizzled [o][k]
        int r = idx >> 6, c = idx & 63;
        *(__nv_bfloat16*)(sm + SM_WB1 + SWZ128((uint32_t)(r * 128 + c * 2))) = g_Wb1[idx];
    }
    for (int idx = tid; idx < DQ * DH; idx += 256) {       // Wb2 swizzled [m][o]
        int r = idx >> 6, c = idx & 63;
        *(__nv_bfloat16*)(sm + SM_WB2 + SWZ128((uint32_t)(r * 128 + c * 2))) = g_Wb2[idx];
    }
    {   // W3 -> bf16 tile [h][k], pitch 80B
        int h = tid >> 5, k = tid & 31;
        *(__nv_bfloat16*)(sm + SM_W3B + h * 80 + k * 2) = __float2bfloat16_rn(W3[tid]);
    }
    if (tid < DH) {
        smf[SM_NI / 4 + tid]  = g_nproj[((size_t)b * NN + i) * DH + tid];
        smf[SM_B1 / 4 + tid]  = g_b1eff[tid];
        smf[SM_W1C / 4 + tid] = g_w1c[tid];
    }
    if (tid < DQ) smf[SM_B2 / 4 + tid] = b2[tid];
    if (tid < HH) smf[SM_B3 / 4 + tid] = b3[tid];

    float cd = chem[((size_t)b * NN + i) * NN + tid];
    cd = fminf(fmaxf(cd, 0.0f), MAXD);
    smf[SM_CD / 4 + tid] = cd;
    smf[SM_MSK / 4 + tid] = (mask[b * NN + i] && mask[b * NN + tid]) ? 1.0f : 0.0f;

    __syncthreads();   // shared state ready

    // ---- ef = tanh(nproj_i + nproj_j): chunked, double-buffered npj ----
    {
        const float* s_ni = smf + SM_NI / 4;
        const float* npT = g_nprojT + (size_t)b * DH * NN + tid;
        float cur[16], nxt[16];
        #pragma unroll
        for (int o = 0; o < 16; ++o) cur[o] = npT[(size_t)o * NN];
        #pragma unroll
        for (int c = 0; c < 4; ++c) {
            if (c < 3) {
                #pragma unroll
                for (int o = 0; o < 16; ++o)
                    nxt[o] = npT[(size_t)((c + 1) * 16 + o) * NN];
            }
            uint32_t ep[8];
            #pragma unroll
            for (int p = 0; p < 8; ++p) {
                float e0 = cur[2*p]     + s_ni[c * 16 + 2*p];
                float e1 = cur[2*p + 1] + s_ni[c * 16 + 2*p + 1];
                uint32_t pk;
                PACK_BF16X2(pk, e0, e1);
                asm("tanh.approx.bf16x2 %0, %0;" : "+r"(pk));
                ep[p] = pk;
            }
            STS128(smb + SM_BUF + SWZ128((uint32_t)(tid * 128 + c * 32)),
                   ep[0], ep[1], ep[2], ep[3]);
            STS128(smb + SM_BUF + SWZ128((uint32_t)(tid * 128 + c * 32 + 16)),
                   ep[4], ep[5], ep[6], ep[7]);
            if (c < 3) {
                #pragma unroll
                for (int o = 0; o < 16; ++o) cur[o] = nxt[o];
            }
        }
    }
    __syncwarp();   // BUF rows are warp-local

    // ================= warp-local tensor pipeline, per 16-row M-tile =================
    const int m_base = wid * 32;
    const int g    = lane >> 2;
    const int tig  = lane & 3;
    const int rA   = m_base + (lane & 15);
    const int chA  = (lane >> 4);
    const int rB2  = (lane & 7);
    const int nsel = (lane >> 4);
    const int chB  = (lane >> 3) & 1;

    // W3 B-fragments + layer-3 biases (loop-invariant)
    uint32_t b3f[2][2];
    #pragma unroll
    for (int kt = 0; kt < 2; ++kt)
        ldsm_x2(b3f[kt], smb + SM_W3B + (uint32_t)(rB2 * 80 + (2*kt + chB) * 16));
    const int c0h = 2 * tig;
    const float b3a = smf[SM_B3 / 4 + c0h], b3b = smf[SM_B3 / 4 + c0h + 1];
    float* outb = out + (size_t)b * HH * NN * NN + (size_t)i * NN;

    #pragma unroll
    for (int mt = 0; mt < 2; ++mt) {
        const int rowb = m_base + mt * 16;

        // layer-1 A-fragments for this 16-row tile
        uint32_t a1f[4][4];
        #pragma unroll
        for (int kt = 0; kt < 4; ++kt)
            ldsm_x4(a1f[kt],
                    smb + SM_BUF + SWZ128((uint32_t)((rA + mt * 16) * 128 + (2*kt + chA) * 16)));

        const float cdl = smf[SM_CD / 4 + rowb + g];
        const float cdh = smf[SM_CD / 4 + rowb + g + 8];

        // ---- layer 1 -> h1 A-fragments (registers) ----
        uint32_t h1A[4][4];
        #pragma unroll
        for (int nbp = 0; nbp < 4; ++nbp) {
            uint32_t bf[4][4];
            #pragma unroll
            for (int kt = 0; kt < 4; ++kt)
                ldsm_x4(bf[kt],
                        smb + SM_WB1 + SWZ128((uint32_t)(((2*nbp + nsel) * 8 + rB2) * 128 + (2*kt + chB) * 16)));
            #pragma unroll
            for (int half = 0; half < 2; ++half) {
                const int nb = 2 * nbp + half;
                const int c0 = nb * 8 + 2 * tig;
                const float b1a = smf[SM_B1 / 4 + c0],  b1b = smf[SM_B1 / 4 + c0 + 1];
                const float wca = smf[SM_W1C / 4 + c0], wcb = smf[SM_W1C / 4 + c0 + 1];
                float d0 = 0.f, d1 = 0.f, d2 = 0.f, d3 = 0.f;
                #pragma unroll
                for (int kt = 0; kt < 4; ++kt)
                    mma16816(d0, d1, d2, d3,
                             a1f[kt][0], a1f[kt][1], a1f[kt][2], a1f[kt][3],
                             bf[kt][2*half], bf[kt][2*half + 1]);
                float v00 = fmaxf(d0 + b1a + cdl * wca, 0.f);
                float v01 = fmaxf(d1 + b1b + cdl * wcb, 0.f);
                float v10 = fmaxf(d2 + b1a + cdh * wca, 0.f);
                float v11 = fmaxf(d3 + b1b + cdh * wcb, 0.f);
                PACK_BF16X2(h1A[nb >> 1][(nb & 1) * 2 + 0], v00, v01);
                PACK_BF16X2(h1A[nb >> 1][(nb & 1) * 2 + 1], v10, v11);
            }
        }

        // ---- layer 2 -> h2 A-fragments ----
        uint32_t h2A[2][4];
        #pragma unroll
        for (int nbp = 0; nbp < 2; ++nbp) {
            uint32_t bf[4][4];
            #pragma unroll
            for (int kt = 0; kt < 4; ++kt)
                ldsm_x4(bf[kt],
                        smb + SM_WB2 + SWZ128((uint32_t)(((2*nbp + nsel) * 8 + rB2) * 128 + (2*kt + chB) * 16)));
            #pragma unroll
            for (int half = 0; half < 2; ++half) {
                const int nb = 2 * nbp + half;
                const int c0 = nb * 8 + 2 * tig;
                const float b2a = smf[SM_B2 / 4 + c0], b2b = smf[SM_B2 / 4 + c0 + 1];
                float d0 = 0.f, d1 = 0.f, d2 = 0.f, d3 = 0.f;
                #pragma unroll
                for (int kt = 0; kt < 4; ++kt)
                    mma16816(d0, d1, d2, d3,
                             h1A[kt][0], h1A[kt][1], h1A[kt][2], h1A[kt][3],
                             bf[kt][2*half], bf[kt][2*half + 1]);
                float v00 = fmaxf(d0 + b2a, 0.f);
                float v01 = fmaxf(d1 + b2b, 0.f);
                float v10 = fmaxf(d2 + b2a, 0.f);
                float v11 = fmaxf(d3 + b2b, 0.f);
                PACK_BF16X2(h2A[nb >> 1][(nb & 1) * 2 + 0], v00, v01);
                PACK_BF16X2(h2A[nb >> 1][(nb & 1) * 2 + 1], v10, v11);
            }
        }

        // ---- layer 3 + sigmoid + direct masked store ----
        {
            float d0 = 0.f, d1 = 0.f, d2 = 0.f, d3 = 0.f;
            #pragma unroll
            for (int kt = 0; kt < 2; ++kt)
                mma16816(d0, d1, d2, d3,
                         h2A[kt][0], h2A[kt][1], h2A[kt][2], h2A[kt][3],
                         b3f[kt][0], b3f[kt][1]);
            const int row0 = rowb + g;
            const int row1 = row0 + 8;
            const float m0 = smf[SM_MSK / 4 + row0];
            const float m1 = smf[SM_MSK / 4 + row1];
            float t0 = (d0 + b3a) * 0.5f, t1 = (d1 + b3b) * 0.5f;
            float t2 = (d2 + b3a) * 0.5f, t3 = (d3 + b3b) * 0.5f;
            asm("tanh.approx.f32 %0, %0;" : "+f"(t0));
            asm("tanh.approx.f32 %0, %0;" : "+f"(t1));
            asm("tanh.approx.f32 %0, %0;" : "+f"(t2));
            asm("tanh.approx.f32 %0, %0;" : "+f"(t3));
            outb[(size_t)(c0h    ) * NN * NN + row0] = fmaf(t0, 0.5f, 0.5f) * m0;
            outb[(size_t)(c0h + 1) * NN * NN + row0] = fmaf(t1, 0.5f, 0.5f) * m0;
            outb[(size_t)(c0h    ) * NN * NN + row1] = fmaf(t2, 0.5f, 0.5f) * m1;
            outb[(size_t)(c0h + 1) * NN * NN + row1] = fmaf(t3, 0.5f, 0.5f) * m1;
        }
    }
}

// ---------------------------------------------------------------------------
extern "C" void kernel_launch(void* const* d_in, const int* in_sizes, int n_in,
                              void* d_out, int out_size) {
    const float* nf     = (const float*)d_in[0];
    const float* chem   = (const float*)d_in[1];
    const int*   mask   = (const int*)d_in[2];     // bool stored as int32
    const float* W_node = (const float*)d_in[3];
    const float* b_node = (const float*)d_in[4];
    const float* W_edge = (const float*)d_in[5];
    const float* b_edge = (const float*)d_in[6];
    const float* W1     = (const float*)d_in[7];
    const float* b1     = (const float*)d_in[8];
    const float* W2     = (const float*)d_in[9];
    const float* b2     = (const float*)d_in[10];
    const float* W3     = (const float*)d_in[11];
    const float* b3     = (const float*)d_in[12];
    float* out = (float*)d_out;

    cudaFuncSetAttribute(sparsity_main_kernel,
                         cudaFuncAttributeMaxDynamicSharedMemorySize, SM_TOTAL);

    prep1_kernel<<<DH + DQ + DD, DH>>>(W_node, W_edge, b_edge, W1, b1, W2);
    prep2_kernel<<<BB * NN, DH>>>(nf, b_node);

    dim3 grid(NN, BB);
    sparsity_main_kernel<<<grid, 256, SM_TOTAL>>>(chem, mask, b2, W3, b3, out);
}

// round 15
// speedup vs baseline: 1.1034x; 1.1034x over previous
#include <cuda_runtime.h>
#include <cuda_bf16.h>
#include <cstdint>

#define BB 8
#define NN 256
#define DD 128
#define HH 8
#define DH 64
#define DQ 32
#define MAXD 5.0f

// ---------------- device scratch (no allocation allowed) ----------------
__device__ float         g_nproj[BB * NN * DH];    // [B,N,64] row-major
__device__ float4        g_nprojT4[BB * 16 * NN];  // [B,o/4,N] float4 (coalesced j-reads)
__device__ float         g_WnT[DD * DH];           // W_node transposed [k][o]
__device__ __nv_bfloat16 g_Wb1[DH * DH];           // folded layer-1 weight [o][k] bf16
__device__ __nv_bfloat16 g_Wb2[DQ * DH];           // W2 [m][o] bf16
__device__ float         g_b1eff[DH];
__device__ float         g_w1c[DH];                // W1[:,96]/MAXD

// ---------------- helpers ----------------
__device__ __forceinline__ uint32_t smem_u32(const void* p) {
    uint32_t a;
    asm("{ .reg .u64 t; cvta.to.shared.u64 t, %1; cvt.u32.u64 %0, t; }" : "=r"(a) : "l"(p));
    return a;
}
#define SWZ128(off) ((off) ^ (((off) >> 3) & 0x70))

#define PACK_BF16X2(res, a, b) \
    asm("cvt.rn.satfinite.bf16x2.f32 %0, %1, %2;" : "=r"(res) : "f"(b), "f"(a))

#define STS128(a, r0, r1, r2, r3) \
    asm volatile("st.shared.v4.b32 [%0], {%1,%2,%3,%4};" :: "r"(a), "r"(r0), "r"(r1), "r"(r2), "r"(r3) : "memory")

__device__ __forceinline__ void ldsm_x4(uint32_t* r, uint32_t addr) {
    asm volatile("ldmatrix.sync.aligned.m8n8.x4.shared.b16 {%0,%1,%2,%3}, [%4];"
                 : "=r"(r[0]), "=r"(r[1]), "=r"(r[2]), "=r"(r[3]) : "r"(addr));
}
__device__ __forceinline__ void ldsm_x2(uint32_t* r, uint32_t addr) {
    asm volatile("ldmatrix.sync.aligned.m8n8.x2.shared.b16 {%0,%1}, [%2];"
                 : "=r"(r[0]), "=r"(r[1]) : "r"(addr));
}
__device__ __forceinline__ void mma16816(float& d0, float& d1, float& d2, float& d3,
                                         uint32_t a0, uint32_t a1, uint32_t a2, uint32_t a3,
                                         uint32_t b0, uint32_t b1) {
    asm volatile("mma.sync.aligned.m16n8k16.row.col.f32.bf16.bf16.f32 "
                 "{%0,%1,%2,%3}, {%4,%5,%6,%7}, {%8,%9}, {%0,%1,%2,%3};"
                 : "+f"(d0), "+f"(d1), "+f"(d2), "+f"(d3)
                 : "r"(a0), "r"(a1), "r"(a2), "r"(a3), "r"(b0), "r"(b1));
}

// ---------------- SMEM layout (dynamic) ----------------
#define SM_BUF   0        // 256 rows x 128B (ef, bf16, swizzled)   (32768)
#define SM_WB1   32768    // 64 x 128B swizzled                      (8192)
#define SM_WB2   40960    // 32 x 128B swizzled                      (4096)
#define SM_W3B   45056    // 8 rows x 80B bf16                       (640)
#define SM_CD    45696    // 256 f                                   (1024)
#define SM_MSK   46720    // 256 f                                   (1024)
#define SM_NI    47744    // 64 f
#define SM_B1    48000    // 64 f
#define SM_W1C   48256    // 64 f
#define SM_B2    48512    // 32 f
#define SM_B3    48640    // 8 f
#define SM_TOTAL 48672

// ---------------------------------------------------------------------------
// prep1: weight folding to bf16 + W_node transpose. grid 224 x 64 threads.
// ---------------------------------------------------------------------------
__global__ void prep1_kernel(const float* __restrict__ Wn,
                             const float* __restrict__ W_edge,
                             const float* __restrict__ b_edge,
                             const float* __restrict__ W1,
                             const float* __restrict__ b1,
                             const float* __restrict__ W2) {
    const int blk = blockIdx.x;
    const int t = threadIdx.x;   // 64 threads
    if (blk < DH) {
        int o = blk, k = t;
        float acc = W1[o * 97 + k];
        #pragma unroll
        for (int m = 0; m < DQ; ++m)
            acc = fmaf(W1[o * 97 + 64 + m], W_edge[m * DD + k], acc);
        g_Wb1[o * DH + k] = __float2bfloat16_rn(acc);
        if (k == 0) {
            float bb = b1[o];
            #pragma unroll
            for (int m = 0; m < DQ; ++m)
                bb = fmaf(W1[o * 97 + 64 + m], b_edge[m], bb);
            g_b1eff[o] = bb;
            g_w1c[o] = W1[o * 97 + 96] * (1.0f / MAXD);
        }
    } else if (blk < DH + DQ) {
        int m = blk - DH;
        g_Wb2[m * DH + t] = __float2bfloat16_rn(W2[m * DH + t]);
    } else {
        int k = blk - (DH + DQ);          // 0..127
        g_WnT[k * DH + t] = Wn[t * DD + k];
    }
}

// ---------------------------------------------------------------------------
// prep2: nproj row; writes row-major + float4-interleaved o-major copies.
// ---------------------------------------------------------------------------
__global__ void prep2_kernel(const float* __restrict__ nf,
                             const float* __restrict__ bn) {
    const int row = blockIdx.x;           // b*256 + n
    const int o = threadIdx.x;            // 64 threads
    __shared__ float sx[DD];
    const float* x = nf + (size_t)row * DD;
    sx[o] = x[o];
    sx[o + 64] = x[o + 64];
    __syncthreads();
    float a0 = 0.f, a1 = 0.f, a2 = 0.f, a3 = 0.f;
    #pragma unroll
    for (int k = 0; k < DD; k += 4) {
        a0 = fmaf(g_WnT[(k + 0) * DH + o], sx[k + 0], a0);
        a1 = fmaf(g_WnT[(k + 1) * DH + o], sx[k + 1], a1);
        a2 = fmaf(g_WnT[(k + 2) * DH + o], sx[k + 2], a2);
        a3 = fmaf(g_WnT[(k + 3) * DH + o], sx[k + 3], a3);
    }
    const float v = (a0 + a1) + (a2 + a3) + bn[o];
    g_nproj[row * DH + o] = v;
    const int b = row >> 8, n = row & 255;
    ((float*)g_nprojT4)[(((size_t)b * 16 + (o >> 2)) * NN + n) * 4 + (o & 3)] = v;
}

// ---------------------------------------------------------------------------
// Main: CTA per (b,i). All 3 layers on mma.sync bf16; register chaining.
// (R11 structure; float2 bias loads + float4 npj loads.)
// ---------------------------------------------------------------------------
__global__ __launch_bounds__(256, 2)
void sparsity_main_kernel(const float* __restrict__ chem,
                          const int* __restrict__ mask,
                          const float* __restrict__ b2,
                          const float* __restrict__ W3,
                          const float* __restrict__ b3,
                          float* __restrict__ out) {
    const int i = blockIdx.x;
    const int b = blockIdx.y;
    const int tid = threadIdx.x;            // == row j
    const int lane = tid & 31;
    const int wid = tid >> 5;

    extern __shared__ char sm[];
    const uint32_t smb = smem_u32(sm);
    float* smf = (float*)sm;

    // ---- cooperative smem fills ----
    for (int idx = tid; idx < DH * DH; idx += 256) {       // Wb1 swizzled [o][k]
        int r = idx >> 6, c = idx & 63;
        *(__nv_bfloat16*)(sm + SM_WB1 + SWZ128((uint32_t)(r * 128 + c * 2))) = g_Wb1[idx];
    }
    for (int idx = tid; idx < DQ * DH; idx += 256) {       // Wb2 swizzled [m][o]
        int r = idx >> 6, c = idx & 63;
        *(__nv_bfloat16*)(sm + SM_WB2 + SWZ128((uint32_t)(r * 128 + c * 2))) = g_Wb2[idx];
    }
    {   // W3 -> bf16 tile [h][k], pitch 80B
        int h = tid >> 5, k = tid & 31;
        *(__nv_bfloat16*)(sm + SM_W3B + h * 80 + k * 2) = __float2bfloat16_rn(W3[tid]);
    }
    if (tid < DH) {
        smf[SM_NI / 4 + tid]  = g_nproj[((size_t)b * NN + i) * DH + tid];
        smf[SM_B1 / 4 + tid]  = g_b1eff[tid];
        smf[SM_W1C / 4 + tid] = g_w1c[tid];
    }
    if (tid < DQ) smf[SM_B2 / 4 + tid] = b2[tid];
    if (tid < HH) smf[SM_B3 / 4 + tid] = b3[tid];

    // per-thread row data: float4 coalesced npj load
    float npj[DH];
    {
        const float4* npT = g_nprojT4 + (size_t)b * 16 * NN + tid;
        #pragma unroll
        for (int q = 0; q < 16; ++q) {
            float4 v = npT[(size_t)q * NN];
            npj[4*q] = v.x; npj[4*q+1] = v.y; npj[4*q+2] = v.z; npj[4*q+3] = v.w;
        }
    }
    float cd = chem[((size_t)b * NN + i) * NN + tid];
    cd = fminf(fmaxf(cd, 0.0f), MAXD);
    smf[SM_CD / 4 + tid] = cd;
    smf[SM_MSK / 4 + tid] = (mask[b * NN + i] && mask[b * NN + tid]) ? 1.0f : 0.0f;

    __syncthreads();   // shared state ready

    // ---- ef = tanh(nproj_i + nproj_j) via bf16x2 MUFU -> swizzled BUF ----
    {
        const float* s_ni = smf + SM_NI / 4;
        uint32_t efp[DH / 2];
        #pragma unroll
        for (int p = 0; p < DH / 2; ++p) {
            float e0 = npj[2*p]     + s_ni[2*p];
            float e1 = npj[2*p + 1] + s_ni[2*p + 1];
            uint32_t pk;
            PACK_BF16X2(pk, e0, e1);
            asm("tanh.approx.bf16x2 %0, %0;" : "+r"(pk));
            efp[p] = pk;
        }
        #pragma unroll
        for (int c = 0; c < 8; ++c) {
            uint32_t off = SWZ128((uint32_t)(tid * 128 + c * 16));
            STS128(smb + SM_BUF + off, efp[4*c], efp[4*c+1], efp[4*c+2], efp[4*c+3]);
        }
    }
    __syncwarp();   // BUF rows are warp-local

    // ================= warp-local tensor pipeline =================
    const int m_base = wid * 32;
    const int g    = lane >> 2;
    const int tig  = lane & 3;
    const int rA   = m_base + (lane & 15);
    const int chA  = (lane >> 4);
    const int rB2  = (lane & 7);
    const int nsel = (lane >> 4);
    const int chB  = (lane >> 3) & 1;

    // ---- layer 1: A-frags from ef ----
    uint32_t a1f[2][4][4];
    #pragma unroll
    for (int mt = 0; mt < 2; ++mt)
        #pragma unroll
        for (int kt = 0; kt < 4; ++kt)
            ldsm_x4(a1f[mt][kt],
                    smb + SM_BUF + SWZ128((uint32_t)((rA + mt * 16) * 128 + (2*kt + chA) * 16)));

    float cdA[2][2];
    #pragma unroll
    for (int mt = 0; mt < 2; ++mt) {
        cdA[mt][0] = smf[SM_CD / 4 + m_base + mt * 16 + g];
        cdA[mt][1] = smf[SM_CD / 4 + m_base + mt * 16 + g + 8];
    }

    // h1 as layer-2 A-fragments (register chaining)
    uint32_t h1A[2][4][4];
    #pragma unroll
    for (int nbp = 0; nbp < 4; ++nbp) {
        uint32_t bf[4][4];
        #pragma unroll
        for (int kt = 0; kt < 4; ++kt)
            ldsm_x4(bf[kt],
                    smb + SM_WB1 + SWZ128((uint32_t)(((2*nbp + nsel) * 8 + rB2) * 128 + (2*kt + chB) * 16)));
        #pragma unroll
        for (int half = 0; half < 2; ++half) {
            const int nb = 2 * nbp + half;
            const int c0 = nb * 8 + 2 * tig;
            const float2 b1p = *(const float2*)(smf + SM_B1 / 4 + c0);
            const float2 wcp = *(const float2*)(smf + SM_W1C / 4 + c0);
            #pragma unroll
            for (int mt = 0; mt < 2; ++mt) {
                float d0 = 0.f, d1 = 0.f, d2 = 0.f, d3 = 0.f;
                #pragma unroll
                for (int kt = 0; kt < 4; ++kt)
                    mma16816(d0, d1, d2, d3,
                             a1f[mt][kt][0], a1f[mt][kt][1], a1f[mt][kt][2], a1f[mt][kt][3],
                             bf[kt][2*half], bf[kt][2*half + 1]);
                float v00 = fmaxf(d0 + b1p.x + cdA[mt][0] * wcp.x, 0.f);
                float v01 = fmaxf(d1 + b1p.y + cdA[mt][0] * wcp.y, 0.f);
                float v10 = fmaxf(d2 + b1p.x + cdA[mt][1] * wcp.x, 0.f);
                float v11 = fmaxf(d3 + b1p.y + cdA[mt][1] * wcp.y, 0.f);
                PACK_BF16X2(h1A[mt][nb >> 1][(nb & 1) * 2 + 0], v00, v01);
                PACK_BF16X2(h1A[mt][nb >> 1][(nb & 1) * 2 + 1], v10, v11);
            }
        }
    }

    // ---- layer 2: A from h1A; h2 as layer-3 A-fragments ----
    uint32_t h2A[2][2][4];
    #pragma unroll
    for (int nbp = 0; nbp < 2; ++nbp) {
        uint32_t bf[4][4];
        #pragma unroll
        for (int kt = 0; kt < 4; ++kt)
            ldsm_x4(bf[kt],
                    smb + SM_WB2 + SWZ128((uint32_t)(((2*nbp + nsel) * 8 + rB2) * 128 + (2*kt + chB) * 16)));
        #pragma unroll
        for (int half = 0; half < 2; ++half) {
            const int nb = 2 * nbp + half;
            const int c0 = nb * 8 + 2 * tig;
            const float2 b2p = *(const float2*)(smf + SM_B2 / 4 + c0);
            #pragma unroll
            for (int mt = 0; mt < 2; ++mt) {
                float d0 = 0.f, d1 = 0.f, d2 = 0.f, d3 = 0.f;
                #pragma unroll
                for (int kt = 0; kt < 4; ++kt)
                    mma16816(d0, d1, d2, d3,
                             h1A[mt][kt][0], h1A[mt][kt][1], h1A[mt][kt][2], h1A[mt][kt][3],
                             bf[kt][2*half], bf[kt][2*half + 1]);
                float v00 = fmaxf(d0 + b2p.x, 0.f);
                float v01 = fmaxf(d1 + b2p.y, 0.f);
                float v10 = fmaxf(d2 + b2p.x, 0.f);
                float v11 = fmaxf(d3 + b2p.y, 0.f);
                PACK_BF16X2(h2A[mt][nb >> 1][(nb & 1) * 2 + 0], v00, v01);
                PACK_BF16X2(h2A[mt][nb >> 1][(nb & 1) * 2 + 1], v10, v11);
            }
        }
    }

    // ---- layer 3 MMA: sigmoid + direct masked store ----
    {
        uint32_t b3f[2][2];
        #pragma unroll
        for (int kt = 0; kt < 2; ++kt)
            ldsm_x2(b3f[kt], smb + SM_W3B + (uint32_t)(rB2 * 80 + (2*kt + chB) * 16));

        const int c0 = 2 * tig;                 // h indices c0, c0+1
        const float2 b3p = *(const float2*)(smf + SM_B3 / 4 + c0);
        float* outb = out + (size_t)b * HH * NN * NN + (size_t)i * NN;

        #pragma unroll
        for (int mt = 0; mt < 2; ++mt) {
            float d0 = 0.f, d1 = 0.f, d2 = 0.f, d3 = 0.f;
            #pragma unroll
            for (int kt = 0; kt < 2; ++kt)
                mma16816(d0, d1, d2, d3,
                         h2A[mt][kt][0], h2A[mt][kt][1], h2A[mt][kt][2], h2A[mt][kt][3],
                         b3f[kt][0], b3f[kt][1]);
            const int row0 = m_base + mt * 16 + g;
            const int row1 = row0 + 8;
            const float m0 = smf[SM_MSK / 4 + row0];
            const float m1 = smf[SM_MSK / 4 + row1];
            float t0 = (d0 + b3p.x) * 0.5f, t1 = (d1 + b3p.y) * 0.5f;
            float t2 = (d2 + b3p.x) * 0.5f, t3 = (d3 + b3p.y) * 0.5f;
            asm("tanh.approx.f32 %0, %0;" : "+f"(t0));
            asm("tanh.approx.f32 %0, %0;" : "+f"(t1));
            asm("tanh.approx.f32 %0, %0;" : "+f"(t2));
            asm("tanh.approx.f32 %0, %0;" : "+f"(t3));
            outb[(size_t)(c0    ) * NN * NN + row0] = fmaf(t0, 0.5f, 0.5f) * m0;
            outb[(size_t)(c0 + 1) * NN * NN + row0] = fmaf(t1, 0.5f, 0.5f) * m0;
            outb[(size_t)(c0    ) * NN * NN + row1] = fmaf(t2, 0.5f, 0.5f) * m1;
            outb[(size_t)(c0 + 1) * NN * NN + row1] = fmaf(t3, 0.5f, 0.5f) * m1;
        }
    }
}

// ---------------------------------------------------------------------------
extern "C" void kernel_launch(void* const* d_in, const int* in_sizes, int n_in,
                              void* d_out, int out_size) {
    const float* nf     = (const float*)d_in[0];
    const float* chem   = (const float*)d_in[1];
    const int*   mask   = (const int*)d_in[2];     // bool stored as int32
    const float* W_node = (const float*)d_in[3];
    const float* b_node = (const float*)d_in[4];
    const float* W_edge = (const float*)d_in[5];
    const float* b_edge = (const float*)d_in[6];
    const float* W1     = (const float*)d_in[7];
    const float* b1     = (const float*)d_in[8];
    const float* W2     = (const float*)d_in[9];
    const float* b2     = (const float*)d_in[10];
    const float* W3     = (const float*)d_in[11];
    const float* b3     = (const float*)d_in[12];
    float* out = (float*)d_out;

    cudaFuncSetAttribute(sparsity_main_kernel,
                         cudaFuncAttributeMaxDynamicSharedMemorySize, SM_TOTAL);

    prep1_kernel<<<DH + DQ + DD, DH>>>(W_node, W_edge, b_edge, W1, b1, W2);
    prep2_kernel<<<BB * NN, DH>>>(nf, b_node);

    dim3 grid(NN, BB);
    sparsity_main_kernel<<<grid, 256, SM_TOTAL>>>(chem, mask, b2, W3, b3, out);
}

// round 16
// speedup vs baseline: 1.4470x; 1.3114x over previous
#include <cuda_runtime.h>
#include <cuda_bf16.h>
#include <cstdint>

#define BB 8
#define NN 256
#define DD 128
#define HH 8
#define DH 64
#define DQ 32
#define MAXD 5.0f

// ---------------- device scratch (no allocation allowed) ----------------
__device__ float         g_nproj[BB * NN * DH];    // [B,N,64] row-major
__device__ float4        g_nprojT4[BB * 16 * NN];  // [B,o/4,N] float4 (coalesced j-reads)
__device__ float         g_WnT[DD * DH];           // W_node transposed [k][o]
__device__ uint4         g_Wb1s[DH * DH * 2 / 16]; // folded layer-1 weight, PRE-SWIZZLED bf16 bytes
__device__ uint4         g_Wb2s[DQ * DH * 2 / 16]; // W2, PRE-SWIZZLED bf16 bytes
__device__ __nv_bfloat16 g_W3b[HH * DQ];           // W3 bf16 [h][k]
__device__ float         g_b1eff[DH];
__device__ float         g_w1c[DH];                // W1[:,96]/MAXD

// ---------------- helpers ----------------
__device__ __forceinline__ uint32_t smem_u32(const void* p) {
    uint32_t a;
    asm("{ .reg .u64 t; cvta.to.shared.u64 t, %1; cvt.u32.u64 %0, t; }" : "=r"(a) : "l"(p));
    return a;
}
#define SWZ128(off) ((off) ^ (((off) >> 3) & 0x70))

#define PACK_BF16X2(res, a, b) \
    asm("cvt.rn.satfinite.bf16x2.f32 %0, %1, %2;" : "=r"(res) : "f"(b), "f"(a))

#define STS128(a, r0, r1, r2, r3) \
    asm volatile("st.shared.v4.b32 [%0], {%1,%2,%3,%4};" :: "r"(a), "r"(r0), "r"(r1), "r"(r2), "r"(r3) : "memory")

#define CPASYNC16(sa, gp) \
    asm volatile("cp.async.cg.shared.global [%0], [%1], 16;" :: "r"(sa), "l"(gp) : "memory")
#define CPASYNC_WAIT() \
    asm volatile("cp.async.commit_group;\n\tcp.async.wait_group 0;" ::: "memory")

__device__ __forceinline__ void ldsm_x4(uint32_t* r, uint32_t addr) {
    asm volatile("ldmatrix.sync.aligned.m8n8.x4.shared.b16 {%0,%1,%2,%3}, [%4];"
                 : "=r"(r[0]), "=r"(r[1]), "=r"(r[2]), "=r"(r[3]) : "r"(addr));
}
__device__ __forceinline__ void ldsm_x2(uint32_t* r, uint32_t addr) {
    asm volatile("ldmatrix.sync.aligned.m8n8.x2.shared.b16 {%0,%1}, [%2];"
                 : "=r"(r[0]), "=r"(r[1]) : "r"(addr));
}
__device__ __forceinline__ void mma16816(float& d0, float& d1, float& d2, float& d3,
                                         uint32_t a0, uint32_t a1, uint32_t a2, uint32_t a3,
                                         uint32_t b0, uint32_t b1) {
    asm volatile("mma.sync.aligned.m16n8k16.row.col.f32.bf16.bf16.f32 "
                 "{%0,%1,%2,%3}, {%4,%5,%6,%7}, {%8,%9}, {%0,%1,%2,%3};"
                 : "+f"(d0), "+f"(d1), "+f"(d2), "+f"(d3)
                 : "r"(a0), "r"(a1), "r"(a2), "r"(a3), "r"(b0), "r"(b1));
}

// ---------------- SMEM layout (dynamic) ----------------
#define SM_BUF   0        // 256 rows x 128B (ef, bf16, swizzled)   (32768)
#define SM_WB1   32768    // 64 x 128B swizzled                      (8192)
#define SM_WB2   40960    // 32 x 128B swizzled                      (4096)
#define SM_W3B   45056    // 8 rows x 80B bf16                       (640)
#define SM_CD    45696    // 256 f                                   (1024)
#define SM_MSK   46720    // 256 f                                   (1024)
#define SM_NI    47744    // 64 f
#define SM_B1    48000    // 64 f
#define SM_W1C   48256    // 64 f
#define SM_B2    48512    // 32 f
#define SM_B3    48640    // 8 f
#define SM_TOTAL 48672

// ---------------------------------------------------------------------------
// prep1: weight folding to PRE-SWIZZLED bf16 + W_node transpose + W3 bf16.
// grid 224 x 64 threads.
// ---------------------------------------------------------------------------
__global__ void prep1_kernel(const float* __restrict__ Wn,
                             const float* __restrict__ W_edge,
                             const float* __restrict__ b_edge,
                             const float* __restrict__ W1,
                             const float* __restrict__ b1,
                             const float* __restrict__ W2,
                             const float* __restrict__ W3) {
    const int blk = blockIdx.x;
    const int t = threadIdx.x;   // 64 threads
    if (blk < DH) {
        int o = blk, k = t;
        float acc = W1[o * 97 + k];
        #pragma unroll
        for (int m = 0; m < DQ; ++m)
            acc = fmaf(W1[o * 97 + 64 + m], W_edge[m * DD + k], acc);
        *(__nv_bfloat16*)((char*)g_Wb1s + SWZ128((uint32_t)(o * 128 + k * 2)))
            = __float2bfloat16_rn(acc);
        if (k == 0) {
            float bb = b1[o];
            #pragma unroll
            for (int m = 0; m < DQ; ++m)
                bb = fmaf(W1[o * 97 + 64 + m], b_edge[m], bb);
            g_b1eff[o] = bb;
            g_w1c[o] = W1[o * 97 + 96] * (1.0f / MAXD);
        }
    } else if (blk < DH + DQ) {
        int m = blk - DH;
        *(__nv_bfloat16*)((char*)g_Wb2s + SWZ128((uint32_t)(m * 128 + t * 2)))
            = __float2bfloat16_rn(W2[m * DH + t]);
    } else {
        int k = blk - (DH + DQ);          // 0..127
        g_WnT[k * DH + t] = Wn[t * DD + k];
        int gid = k * DH + t;
        if (gid < HH * DQ)
            g_W3b[gid] = __float2bfloat16_rn(W3[gid]);
    }
}

// ---------------------------------------------------------------------------
// prep2: nproj row; writes row-major + float4-interleaved o-major copies.
// ---------------------------------------------------------------------------
__global__ void prep2_kernel(const float* __restrict__ nf,
                             const float* __restrict__ bn) {
    const int row = blockIdx.x;           // b*256 + n
    const int o = threadIdx.x;            // 64 threads
    __shared__ float sx[DD];
    const float* x = nf + (size_t)row * DD;
    sx[o] = x[o];
    sx[o + 64] = x[o + 64];
    __syncthreads();
    float a0 = 0.f, a1 = 0.f, a2 = 0.f, a3 = 0.f;
    #pragma unroll
    for (int k = 0; k < DD; k += 4) {
        a0 = fmaf(g_WnT[(k + 0) * DH + o], sx[k + 0], a0);
        a1 = fmaf(g_WnT[(k + 1) * DH + o], sx[k + 1], a1);
        a2 = fmaf(g_WnT[(k + 2) * DH + o], sx[k + 2], a2);
        a3 = fmaf(g_WnT[(k + 3) * DH + o], sx[k + 3], a3);
    }
    const float v = (a0 + a1) + (a2 + a3) + bn[o];
    g_nproj[row * DH + o] = v;
    const int b = row >> 8, n = row & 255;
    ((float*)g_nprojT4)[(((size_t)b * 16 + (o >> 2)) * NN + n) * 4 + (o & 3)] = v;
}

// ---------------------------------------------------------------------------
// Main: CTA per (b,i). All 3 layers on mma.sync bf16; register chaining.
// Pre-swizzled weights copied via cp.async (overlaps npj/cd LDGs).
// ---------------------------------------------------------------------------
__global__ __launch_bounds__(256, 2)
void sparsity_main_kernel(const float* __restrict__ chem,
                          const int* __restrict__ mask,
                          const float* __restrict__ b2,
                          const float* __restrict__ b3,
                          float* __restrict__ out) {
    const int i = blockIdx.x;
    const int b = blockIdx.y;
    const int tid = threadIdx.x;            // == row j
    const int lane = tid & 31;
    const int wid = tid >> 5;

    extern __shared__ char sm[];
    const uint32_t smb = smem_u32(sm);
    float* smf = (float*)sm;

    // ---- kick off async weight-tile copies (pre-swizzled, pure 16B chunks) ----
    CPASYNC16(smb + SM_WB1 + tid * 16,        (const char*)g_Wb1s + tid * 16);
    CPASYNC16(smb + SM_WB1 + (tid + 256) * 16,(const char*)g_Wb1s + (tid + 256) * 16);
    CPASYNC16(smb + SM_WB2 + tid * 16,        (const char*)g_Wb2s + tid * 16);

    // ---- per-thread row data (deep-MLP LDGs, overlap the cp.async) ----
    float npj[DH];
    {
        const float4* npT = g_nprojT4 + (size_t)b * 16 * NN + tid;
        #pragma unroll
        for (int q = 0; q < 16; ++q) {
            float4 v = npT[(size_t)q * NN];
            npj[4*q] = v.x; npj[4*q+1] = v.y; npj[4*q+2] = v.z; npj[4*q+3] = v.w;
        }
    }
    float cd = chem[((size_t)b * NN + i) * NN + tid];
    cd = fminf(fmaxf(cd, 0.0f), MAXD);
    smf[SM_CD / 4 + tid] = cd;
    smf[SM_MSK / 4 + tid] = (mask[b * NN + i] && mask[b * NN + tid]) ? 1.0f : 0.0f;

    // ---- small scalar fills ----
    {   // W3 bf16 tile [h][k], pitch 80B
        int h = tid >> 5, k = tid & 31;
        *(__nv_bfloat16*)(sm + SM_W3B + h * 80 + k * 2) = g_W3b[tid];
    }
    if (tid < DH) {
        smf[SM_NI / 4 + tid]  = g_nproj[((size_t)b * NN + i) * DH + tid];
        smf[SM_B1 / 4 + tid]  = g_b1eff[tid];
        smf[SM_W1C / 4 + tid] = g_w1c[tid];
    }
    if (tid < DQ) smf[SM_B2 / 4 + tid] = b2[tid];
    if (tid < HH) smf[SM_B3 / 4 + tid] = b3[tid];

    CPASYNC_WAIT();
    __syncthreads();   // shared state ready

    // ---- ef = tanh(nproj_i + nproj_j) via bf16x2 MUFU -> swizzled BUF ----
    {
        const float* s_ni = smf + SM_NI / 4;
        uint32_t efp[DH / 2];
        #pragma unroll
        for (int p = 0; p < DH / 2; ++p) {
            float e0 = npj[2*p]     + s_ni[2*p];
            float e1 = npj[2*p + 1] + s_ni[2*p + 1];
            uint32_t pk;
            PACK_BF16X2(pk, e0, e1);
            asm("tanh.approx.bf16x2 %0, %0;" : "+r"(pk));
            efp[p] = pk;
        }
        #pragma unroll
        for (int c = 0; c < 8; ++c) {
            uint32_t off = SWZ128((uint32_t)(tid * 128 + c * 16));
            STS128(smb + SM_BUF + off, efp[4*c], efp[4*c+1], efp[4*c+2], efp[4*c+3]);
        }
    }
    __syncwarp();   // BUF rows are warp-local

    // ================= warp-local tensor pipeline =================
    const int m_base = wid * 32;
    const int g    = lane >> 2;
    const int tig  = lane & 3;
    const int rA   = m_base + (lane & 15);
    const int chA  = (lane >> 4);
    const int rB2  = (lane & 7);
    const int nsel = (lane >> 4);
    const int chB  = (lane >> 3) & 1;

    // ---- layer 1: A-frags from ef ----
    uint32_t a1f[2][4][4];
    #pragma unroll
    for (int mt = 0; mt < 2; ++mt)
        #pragma unroll
        for (int kt = 0; kt < 4; ++kt)
            ldsm_x4(a1f[mt][kt],
                    smb + SM_BUF + SWZ128((uint32_t)((rA + mt * 16) * 128 + (2*kt + chA) * 16)));

    float cdA[2][2];
    #pragma unroll
    for (int mt = 0; mt < 2; ++mt) {
        cdA[mt][0] = smf[SM_CD / 4 + m_base + mt * 16 + g];
        cdA[mt][1] = smf[SM_CD / 4 + m_base + mt * 16 + g + 8];
    }

    // h1 as layer-2 A-fragments (register chaining)
    uint32_t h1A[2][4][4];
    #pragma unroll
    for (int nbp = 0; nbp < 4; ++nbp) {
        uint32_t bf[4][4];
        #pragma unroll
        for (int kt = 0; kt < 4; ++kt)
            ldsm_x4(bf[kt],
                    smb + SM_WB1 + SWZ128((uint32_t)(((2*nbp + nsel) * 8 + rB2) * 128 + (2*kt + chB) * 16)));
        #pragma unroll
        for (int half = 0; half < 2; ++half) {
            const int nb = 2 * nbp + half;
            const int c0 = nb * 8 + 2 * tig;
            const float2 b1p = *(const float2*)(smf + SM_B1 / 4 + c0);
            const float2 wcp = *(const float2*)(smf + SM_W1C / 4 + c0);
            #pragma unroll
            for (int mt = 0; mt < 2; ++mt) {
                float d0 = 0.f, d1 = 0.f, d2 = 0.f, d3 = 0.f;
                #pragma unroll
                for (int kt = 0; kt < 4; ++kt)
                    mma16816(d0, d1, d2, d3,
                             a1f[mt][kt][0], a1f[mt][kt][1], a1f[mt][kt][2], a1f[mt][kt][3],
                             bf[kt][2*half], bf[kt][2*half + 1]);
                float v00 = fmaxf(d0 + b1p.x + cdA[mt][0] * wcp.x, 0.f);
                float v01 = fmaxf(d1 + b1p.y + cdA[mt][0] * wcp.y, 0.f);
                float v10 = fmaxf(d2 + b1p.x + cdA[mt][1] * wcp.x, 0.f);
                float v11 = fmaxf(d3 + b1p.y + cdA[mt][1] * wcp.y, 0.f);
                PACK_BF16X2(h1A[mt][nb >> 1][(nb & 1) * 2 + 0], v00, v01);
                PACK_BF16X2(h1A[mt][nb >> 1][(nb & 1) * 2 + 1], v10, v11);
            }
        }
    }

    // ---- layer 2: A from h1A; h2 as layer-3 A-fragments ----
    uint32_t h2A[2][2][4];
    #pragma unroll
    for (int nbp = 0; nbp < 2; ++nbp) {
        uint32_t bf[4][4];
        #pragma unroll
        for (int kt = 0; kt < 4; ++kt)
            ldsm_x4(bf[kt],
                    smb + SM_WB2 + SWZ128((uint32_t)(((2*nbp + nsel) * 8 + rB2) * 128 + (2*kt + chB) * 16)));
        #pragma unroll
        for (int half = 0; half < 2; ++half) {
            const int nb = 2 * nbp + half;
            const int c0 = nb * 8 + 2 * tig;
            const float2 b2p = *(const float2*)(smf + SM_B2 / 4 + c0);
            #pragma unroll
            for (int mt = 0; mt < 2; ++mt) {
                float d0 = 0.f, d1 = 0.f, d2 = 0.f, d3 = 0.f;
                #pragma unroll
                for (int kt = 0; kt < 4; ++kt)
                    mma16816(d0, d1, d2, d3,
                             h1A[mt][kt][0], h1A[mt][kt][1], h1A[mt][kt][2], h1A[mt][kt][3],
                             bf[kt][2*half], bf[kt][2*half + 1]);
                float v00 = fmaxf(d0 + b2p.x, 0.f);
                float v01 = fmaxf(d1 + b2p.y, 0.f);
                float v10 = fmaxf(d2 + b2p.x, 0.f);
                float v11 = fmaxf(d3 + b2p.y, 0.f);
                PACK_BF16X2(h2A[mt][nb >> 1][(nb & 1) * 2 + 0], v00, v01);
                PACK_BF16X2(h2A[mt][nb >> 1][(nb & 1) * 2 + 1], v10, v11);
            }
        }
    }

    // ---- layer 3 MMA: sigmoid + direct masked store ----
    {
        uint32_t b3f[2][2];
        #pragma unroll
        for (int kt = 0; kt < 2; ++kt)
            ldsm_x2(b3f[kt], smb + SM_W3B + (uint32_t)(rB2 * 80 + (2*kt + chB) * 16));

        const int c0 = 2 * tig;                 // h indices c0, c0+1
        const float2 b3p = *(const float2*)(smf + SM_B3 / 4 + c0);
        float* outb = out + (size_t)b * HH * NN * NN + (size_t)i * NN;

        #pragma unroll
        for (int mt = 0; mt < 2; ++mt) {
            float d0 = 0.f, d1 = 0.f, d2 = 0.f, d3 = 0.f;
            #pragma unroll
            for (int kt = 0; kt < 2; ++kt)
                mma16816(d0, d1, d2, d3,
                         h2A[mt][kt][0], h2A[mt][kt][1], h2A[mt][kt][2], h2A[mt][kt][3],
                         b3f[kt][0], b3f[kt][1]);
            const int row0 = m_base + mt * 16 + g;
            const int row1 = row0 + 8;
            const float m0 = smf[SM_MSK / 4 + row0];
            const float m1 = smf[SM_MSK / 4 + row1];
            float t0 = (d0 + b3p.x) * 0.5f, t1 = (d1 + b3p.y) * 0.5f;
            float t2 = (d2 + b3p.x) * 0.5f, t3 = (d3 + b3p.y) * 0.5f;
            asm("tanh.approx.f32 %0, %0;" : "+f"(t0));
            asm("tanh.approx.f32 %0, %0;" : "+f"(t1));
            asm("tanh.approx.f32 %0, %0;" : "+f"(t2));
            asm("tanh.approx.f32 %0, %0;" : "+f"(t3));
            outb[(size_t)(c0    ) * NN * NN + row0] = fmaf(t0, 0.5f, 0.5f) * m0;
            outb[(size_t)(c0 + 1) * NN * NN + row0] = fmaf(t1, 0.5f, 0.5f) * m0;
            outb[(size_t)(c0    ) * NN * NN + row1] = fmaf(t2, 0.5f, 0.5f) * m1;
            outb[(size_t)(c0 + 1) * NN * NN + row1] = fmaf(t3, 0.5f, 0.5f) * m1;
        }
    }
}

// ---------------------------------------------------------------------------
extern "C" void kernel_launch(void* const* d_in, const int* in_sizes, int n_in,
                              void* d_out, int out_size) {
    const float* nf     = (const float*)d_in[0];
    const float* chem   = (const float*)d_in[1];
    const int*   mask   = (const int*)d_in[2];     // bool stored as int32
    const float* W_node = (const float*)d_in[3];
    const float* b_node = (const float*)d_in[4];
    const float* W_edge = (const float*)d_in[5];
    const float* b_edge = (const float*)d_in[6];
    const float* W1     = (const float*)d_in[7];
    const float* b1     = (const float*)d_in[8];
    const float* W2     = (const float*)d_in[9];
    const float* b2     = (const float*)d_in[10];
    const float* W3     = (const float*)d_in[11];
    const float* b3     = (const float*)d_in[12];
    float* out = (float*)d_out;

    cudaFuncSetAttribute(sparsity_main_kernel,
                         cudaFuncAttributeMaxDynamicSharedMemorySize, SM_TOTAL);

    prep1_kernel<<<DH + DQ + DD, DH>>>(W_node, W_edge, b_edge, W1, b1, W2, W3);
    prep2_kernel<<<BB * NN, DH>>>(nf, b_node);

    dim3 grid(NN, BB);
    sparsity_main_kernel<<<grid, 256, SM_TOTAL>>>(chem, mask, b2, b3, out);
}

// round 17
// speedup vs baseline: 1.5605x; 1.0784x over previous
#include <cuda_runtime.h>
#include <cuda_bf16.h>
#include <cstdint>

#define BB 8
#define NN 256
#define DD 128
#define HH 8
#define DH 64
#define DQ 32
#define MAXD 5.0f

// ---------------- device scratch (no allocation allowed) ----------------
__device__ float         g_nproj[BB * NN * DH];    // [B,N,64] row-major
__device__ float4        g_nprojT4[BB * 16 * NN];  // [B,o/4,N] float4 (coalesced j-reads)
__device__ uint4         g_Wb1s[DH * DH * 2 / 16]; // folded layer-1 weight, PRE-SWIZZLED bf16 bytes
__device__ uint4         g_Wb2s[DQ * DH * 2 / 16]; // W2, PRE-SWIZZLED bf16 bytes
__device__ __nv_bfloat16 g_W3b[HH * DQ];           // W3 bf16 [h][k]
__device__ float         g_b1eff[DH];
__device__ float         g_w1c[DH];                // W1[:,96]/MAXD

// ---------------- helpers ----------------
__device__ __forceinline__ uint32_t smem_u32(const void* p) {
    uint32_t a;
    asm("{ .reg .u64 t; cvta.to.shared.u64 t, %1; cvt.u32.u64 %0, t; }" : "=r"(a) : "l"(p));
    return a;
}
#define SWZ128(off) ((off) ^ (((off) >> 3) & 0x70))

#define PACK_BF16X2(res, a, b) \
    asm("cvt.rn.satfinite.bf16x2.f32 %0, %1, %2;" : "=r"(res) : "f"(b), "f"(a))

#define STS128(a, r0, r1, r2, r3) \
    asm volatile("st.shared.v4.b32 [%0], {%1,%2,%3,%4};" :: "r"(a), "r"(r0), "r"(r1), "r"(r2), "r"(r3) : "memory")

#define CPASYNC16(sa, gp) \
    asm volatile("cp.async.cg.shared.global [%0], [%1], 16;" :: "r"(sa), "l"(gp) : "memory")
#define CPASYNC_WAIT() \
    asm volatile("cp.async.commit_group;\n\tcp.async.wait_group 0;" ::: "memory")

__device__ __forceinline__ void ldsm_x4(uint32_t* r, uint32_t addr) {
    asm volatile("ldmatrix.sync.aligned.m8n8.x4.shared.b16 {%0,%1,%2,%3}, [%4];"
                 : "=r"(r[0]), "=r"(r[1]), "=r"(r[2]), "=r"(r[3]) : "r"(addr));
}
__device__ __forceinline__ void ldsm_x2(uint32_t* r, uint32_t addr) {
    asm volatile("ldmatrix.sync.aligned.m8n8.x2.shared.b16 {%0,%1}, [%2];"
                 : "=r"(r[0]), "=r"(r[1]) : "r"(addr));
}
__device__ __forceinline__ void mma16816(float& d0, float& d1, float& d2, float& d3,
                                         uint32_t a0, uint32_t a1, uint32_t a2, uint32_t a3,
                                         uint32_t b0, uint32_t b1) {
    asm volatile("mma.sync.aligned.m16n8k16.row.col.f32.bf16.bf16.f32 "
                 "{%0,%1,%2,%3}, {%4,%5,%6,%7}, {%8,%9}, {%0,%1,%2,%3};"
                 : "+f"(d0), "+f"(d1), "+f"(d2), "+f"(d3)
                 : "r"(a0), "r"(a1), "r"(a2), "r"(a3), "r"(b0), "r"(b1));
}

// ---------------- SMEM layout (main kernel, dynamic) ----------------
#define SM_BUF   0        // 256 rows x 128B (ef, bf16, swizzled)   (32768)
#define SM_WB1   32768    // 64 x 128B swizzled                      (8192)
#define SM_WB2   40960    // 32 x 128B swizzled                      (4096)
#define SM_W3B   45056    // 8 rows x 80B bf16                       (640)
#define SM_CD    45696    // 256 f                                   (1024)
#define SM_MSK   46720    // 256 f                                   (1024)
#define SM_NI    47744    // 64 f
#define SM_B1    48000    // 64 f
#define SM_W1C   48256    // 64 f
#define SM_B2    48512    // 32 f
#define SM_B3    48640    // 8 f
#define SM_TOTAL 48672

// ---------------------------------------------------------------------------
// fused prep: ONE launch.
//   blk 0..15 : Wb1 fold -> pre-swizzled bf16 (+ b1eff, w1c)
//   blk 16..23: Wb2 -> pre-swizzled bf16
//   blk 24    : W3 -> bf16
//   blk 25..  : nproj, 16 rows/block; Wn transposed into smem per block
// ---------------------------------------------------------------------------
#define PREP_NPROJ_BLK0 25
#define PREP_ROWS 16

__global__ __launch_bounds__(256)
void prep_kernel(const float* __restrict__ nf,
                 const float* __restrict__ Wn,
                 const float* __restrict__ bn,
                 const float* __restrict__ W_edge,
                 const float* __restrict__ b_edge,
                 const float* __restrict__ W1,
                 const float* __restrict__ b1,
                 const float* __restrict__ W2,
                 const float* __restrict__ W3) {
    const int blk = blockIdx.x;
    const int tid = threadIdx.x;   // 256 threads

    if (blk < 16) {                       // Wb1 fold: 4 o-rows per block
        int o = blk * 4 + (tid >> 6), k = tid & 63;
        float acc = W1[o * 97 + k];
        #pragma unroll
        for (int m = 0; m < DQ; ++m)
            acc = fmaf(W1[o * 97 + 64 + m], W_edge[m * DD + k], acc);
        *(__nv_bfloat16*)((char*)g_Wb1s + SWZ128((uint32_t)(o * 128 + k * 2)))
            = __float2bfloat16_rn(acc);
        if (k == 0) {
            float bb = b1[o];
            #pragma unroll
            for (int m = 0; m < DQ; ++m)
                bb = fmaf(W1[o * 97 + 64 + m], b_edge[m], bb);
            g_b1eff[o] = bb;
            g_w1c[o] = W1[o * 97 + 96] * (1.0f / MAXD);
        }
        return;
    }
    if (blk < 24) {                       // Wb2: 4 m-rows per block
        int m = (blk - 16) * 4 + (tid >> 6), k = tid & 63;
        *(__nv_bfloat16*)((char*)g_Wb2s + SWZ128((uint32_t)(m * 128 + k * 2)))
            = __float2bfloat16_rn(W2[m * DH + k]);
        return;
    }
    if (blk == 24) {                      // W3 -> bf16 (256 entries)
        g_W3b[tid] = __float2bfloat16_rn(W3[tid]);
        return;
    }

    // ---- nproj: 16 rows per block ----
    __shared__ float sWnT[DD * 65];       // Wn transposed [k][o], pitch 65 (33280 B)
    __shared__ float sx[PREP_ROWS * DD];  // 16 node rows (8192 B)

    const int row_base = (blk - PREP_NPROJ_BLK0) * PREP_ROWS;   // b*256+n base

    // load + transpose Wn (coalesced LDG; conflict-free STS: bank=(k+o)%32)
    #pragma unroll
    for (int it = 0; it < 32; ++it) {
        int idx = tid + it * 256;         // o = idx>>7, k = idx&127
        sWnT[(idx & 127) * 65 + (idx >> 7)] = Wn[idx];
    }
    // load 16 nf rows
    #pragma unroll
    for (int it = 0; it < 8; ++it) {
        int idx = tid + it * 256;
        sx[idx] = nf[(size_t)row_base * DD + idx];
    }
    __syncthreads();

    const int o = tid & 63;
    const int rq = tid >> 6;              // 0..3
    const float bo = bn[o];
    #pragma unroll
    for (int rr = 0; rr < 4; ++rr) {
        const int r = rq * 4 + rr;        // 0..15
        const float* x = sx + r * DD;
        float a0 = 0.f, a1 = 0.f, a2 = 0.f, a3 = 0.f;
        #pragma unroll
        for (int k = 0; k < DD; k += 4) {
            a0 = fmaf(sWnT[(k + 0) * 65 + o], x[k + 0], a0);
            a1 = fmaf(sWnT[(k + 1) * 65 + o], x[k + 1], a1);
            a2 = fmaf(sWnT[(k + 2) * 65 + o], x[k + 2], a2);
            a3 = fmaf(sWnT[(k + 3) * 65 + o], x[k + 3], a3);
        }
        const float v = (a0 + a1) + (a2 + a3) + bo;
        const int row = row_base + r;
        g_nproj[row * DH + o] = v;
        const int b = row >> 8, n = row & 255;
        ((float*)g_nprojT4)[(((size_t)b * 16 + (o >> 2)) * NN + n) * 4 + (o & 3)] = v;
    }
}

// ---------------------------------------------------------------------------
// Main: CTA per (b,i). All 3 layers on mma.sync bf16; register chaining.
// Pre-swizzled weights copied via cp.async (overlaps npj/cd LDGs).
// (byte-for-byte R16)
// ---------------------------------------------------------------------------
__global__ __launch_bounds__(256, 2)
void sparsity_main_kernel(const float* __restrict__ chem,
                          const int* __restrict__ mask,
                          const float* __restrict__ b2,
                          const float* __restrict__ b3,
                          float* __restrict__ out) {
    const int i = blockIdx.x;
    const int b = blockIdx.y;
    const int tid = threadIdx.x;            // == row j
    const int lane = tid & 31;
    const int wid = tid >> 5;

    extern __shared__ char sm[];
    const uint32_t smb = smem_u32(sm);
    float* smf = (float*)sm;

    // ---- kick off async weight-tile copies (pre-swizzled, pure 16B chunks) ----
    CPASYNC16(smb + SM_WB1 + tid * 16,        (const char*)g_Wb1s + tid * 16);
    CPASYNC16(smb + SM_WB1 + (tid + 256) * 16,(const char*)g_Wb1s + (tid + 256) * 16);
    CPASYNC16(smb + SM_WB2 + tid * 16,        (const char*)g_Wb2s + tid * 16);

    // ---- per-thread row data (deep-MLP LDGs, overlap the cp.async) ----
    float npj[DH];
    {
        const float4* npT = g_nprojT4 + (size_t)b * 16 * NN + tid;
        #pragma unroll
        for (int q = 0; q < 16; ++q) {
            float4 v = npT[(size_t)q * NN];
            npj[4*q] = v.x; npj[4*q+1] = v.y; npj[4*q+2] = v.z; npj[4*q+3] = v.w;
        }
    }
    float cd = chem[((size_t)b * NN + i) * NN + tid];
    cd = fminf(fmaxf(cd, 0.0f), MAXD);
    smf[SM_CD / 4 + tid] = cd;
    smf[SM_MSK / 4 + tid] = (mask[b * NN + i] && mask[b * NN + tid]) ? 1.0f : 0.0f;

    // ---- small scalar fills ----
    {   // W3 bf16 tile [h][k], pitch 80B
        int h = tid >> 5, k = tid & 31;
        *(__nv_bfloat16*)(sm + SM_W3B + h * 80 + k * 2) = g_W3b[tid];
    }
    if (tid < DH) {
        smf[SM_NI / 4 + tid]  = g_nproj[((size_t)b * NN + i) * DH + tid];
        smf[SM_B1 / 4 + tid]  = g_b1eff[tid];
        smf[SM_W1C / 4 + tid] = g_w1c[tid];
    }
    if (tid < DQ) smf[SM_B2 / 4 + tid] = b2[tid];
    if (tid < HH) smf[SM_B3 / 4 + tid] = b3[tid];

    CPASYNC_WAIT();
    __syncthreads();   // shared state ready

    // ---- ef = tanh(nproj_i + nproj_j) via bf16x2 MUFU -> swizzled BUF ----
    {
        const float* s_ni = smf + SM_NI / 4;
        uint32_t efp[DH / 2];
        #pragma unroll
        for (int p = 0; p < DH / 2; ++p) {
            float e0 = npj[2*p]     + s_ni[2*p];
            float e1 = npj[2*p + 1] + s_ni[2*p + 1];
            uint32_t pk;
            PACK_BF16X2(pk, e0, e1);
            asm("tanh.approx.bf16x2 %0, %0;" : "+r"(pk));
            efp[p] = pk;
        }
        #pragma unroll
        for (int c = 0; c < 8; ++c) {
            uint32_t off = SWZ128((uint32_t)(tid * 128 + c * 16));
            STS128(smb + SM_BUF + off, efp[4*c], efp[4*c+1], efp[4*c+2], efp[4*c+3]);
        }
    }
    __syncwarp();   // BUF rows are warp-local

    // ================= warp-local tensor pipeline =================
    const int m_base = wid * 32;
    const int g    = lane >> 2;
    const int tig  = lane & 3;
    const int rA   = m_base + (lane & 15);
    const int chA  = (lane >> 4);
    const int rB2  = (lane & 7);
    const int nsel = (lane >> 4);
    const int chB  = (lane >> 3) & 1;

    // ---- layer 1: A-frags from ef ----
    uint32_t a1f[2][4][4];
    #pragma unroll
    for (int mt = 0; mt < 2; ++mt)
        #pragma unroll
        for (int kt = 0; kt < 4; ++kt)
            ldsm_x4(a1f[mt][kt],
                    smb + SM_BUF + SWZ128((uint32_t)((rA + mt * 16) * 128 + (2*kt + chA) * 16)));

    float cdA[2][2];
    #pragma unroll
    for (int mt = 0; mt < 2; ++mt) {
        cdA[mt][0] = smf[SM_CD / 4 + m_base + mt * 16 + g];
        cdA[mt][1] = smf[SM_CD / 4 + m_base + mt * 16 + g + 8];
    }

    // h1 as layer-2 A-fragments (register chaining)
    uint32_t h1A[2][4][4];
    #pragma unroll
    for (int nbp = 0; nbp < 4; ++nbp) {
        uint32_t bf[4][4];
        #pragma unroll
        for (int kt = 0; kt < 4; ++kt)
            ldsm_x4(bf[kt],
                    smb + SM_WB1 + SWZ128((uint32_t)(((2*nbp + nsel) * 8 + rB2) * 128 + (2*kt + chB) * 16)));
        #pragma unroll
        for (int half = 0; half < 2; ++half) {
            const int nb = 2 * nbp + half;
            const int c0 = nb * 8 + 2 * tig;
            const float2 b1p = *(const float2*)(smf + SM_B1 / 4 + c0);
            const float2 wcp = *(const float2*)(smf + SM_W1C / 4 + c0);
            #pragma unroll
            for (int mt = 0; mt < 2; ++mt) {
                float d0 = 0.f, d1 = 0.f, d2 = 0.f, d3 = 0.f;
                #pragma unroll
                for (int kt = 0; kt < 4; ++kt)
                    mma16816(d0, d1, d2, d3,
                             a1f[mt][kt][0], a1f[mt][kt][1], a1f[mt][kt][2], a1f[mt][kt][3],
                             bf[kt][2*half], bf[kt][2*half + 1]);
                float v00 = fmaxf(d0 + b1p.x + cdA[mt][0] * wcp.x, 0.f);
                float v01 = fmaxf(d1 + b1p.y + cdA[mt][0] * wcp.y, 0.f);
                float v10 = fmaxf(d2 + b1p.x + cdA[mt][1] * wcp.x, 0.f);
                float v11 = fmaxf(d3 + b1p.y + cdA[mt][1] * wcp.y, 0.f);
                PACK_BF16X2(h1A[mt][nb >> 1][(nb & 1) * 2 + 0], v00, v01);
                PACK_BF16X2(h1A[mt][nb >> 1][(nb & 1) * 2 + 1], v10, v11);
            }
        }
    }

    // ---- layer 2: A from h1A; h2 as layer-3 A-fragments ----
    uint32_t h2A[2][2][4];
    #pragma unroll
    for (int nbp = 0; nbp < 2; ++nbp) {
        uint32_t bf[4][4];
        #pragma unroll
        for (int kt = 0; kt < 4; ++kt)
            ldsm_x4(bf[kt],
                    smb + SM_WB2 + SWZ128((uint32_t)(((2*nbp + nsel) * 8 + rB2) * 128 + (2*kt + chB) * 16)));
        #pragma unroll
        for (int half = 0; half < 2; ++half) {
            const int nb = 2 * nbp + half;
            const int c0 = nb * 8 + 2 * tig;
            const float2 b2p = *(const float2*)(smf + SM_B2 / 4 + c0);
            #pragma unroll
            for (int mt = 0; mt < 2; ++mt) {
                float d0 = 0.f, d1 = 0.f, d2 = 0.f, d3 = 0.f;
                #pragma unroll
                for (int kt = 0; kt < 4; ++kt)
                    mma16816(d0, d1, d2, d3,
                             h1A[mt][kt][0], h1A[mt][kt][1], h1A[mt][kt][2], h1A[mt][kt][3],
                             bf[kt][2*half], bf[kt][2*half + 1]);
                float v00 = fmaxf(d0 + b2p.x, 0.f);
                float v01 = fmaxf(d1 + b2p.y, 0.f);
                float v10 = fmaxf(d2 + b2p.x, 0.f);
                float v11 = fmaxf(d3 + b2p.y, 0.f);
                PACK_BF16X2(h2A[mt][nb >> 1][(nb & 1) * 2 + 0], v00, v01);
                PACK_BF16X2(h2A[mt][nb >> 1][(nb & 1) * 2 + 1], v10, v11);
            }
        }
    }

    // ---- layer 3 MMA: sigmoid + direct masked store ----
    {
        uint32_t b3f[2][2];
        #pragma unroll
        for (int kt = 0; kt < 2; ++kt)
            ldsm_x2(b3f[kt], smb + SM_W3B + (uint32_t)(rB2 * 80 + (2*kt + chB) * 16));

        const int c0 = 2 * tig;                 // h indices c0, c0+1
        const float2 b3p = *(const float2*)(smf + SM_B3 / 4 + c0);
        float* outb = out + (size_t)b * HH * NN * NN + (size_t)i * NN;

        #pragma unroll
        for (int mt = 0; mt < 2; ++mt) {
            float d0 = 0.f, d1 = 0.f, d2 = 0.f, d3 = 0.f;
            #pragma unroll
            for (int kt = 0; kt < 2; ++kt)
                mma16816(d0, d1, d2, d3,
                         h2A[mt][kt][0], h2A[mt][kt][1], h2A[mt][kt][2], h2A[mt][kt][3],
                         b3f[kt][0], b3f[kt][1]);
            const int row0 = m_base + mt * 16 + g;
            const int row1 = row0 + 8;
            const float m0 = smf[SM_MSK / 4 + row0];
            const float m1 = smf[SM_MSK / 4 + row1];
            float t0 = (d0 + b3p.x) * 0.5f, t1 = (d1 + b3p.y) * 0.5f;
            float t2 = (d2 + b3p.x) * 0.5f, t3 = (d3 + b3p.y) * 0.5f;
            asm("tanh.approx.f32 %0, %0;" : "+f"(t0));
            asm("tanh.approx.f32 %0, %0;" : "+f"(t1));
            asm("tanh.approx.f32 %0, %0;" : "+f"(t2));
            asm("tanh.approx.f32 %0, %0;" : "+f"(t3));
            outb[(size_t)(c0    ) * NN * NN + row0] = fmaf(t0, 0.5f, 0.5f) * m0;
            outb[(size_t)(c0 + 1) * NN * NN + row0] = fmaf(t1, 0.5f, 0.5f) * m0;
            outb[(size_t)(c0    ) * NN * NN + row1] = fmaf(t2, 0.5f, 0.5f) * m1;
            outb[(size_t)(c0 + 1) * NN * NN + row1] = fmaf(t3, 0.5f, 0.5f) * m1;
        }
    }
}

// ---------------------------------------------------------------------------
extern "C" void kernel_launch(void* const* d_in, const int* in_sizes, int n_in,
                              void* d_out, int out_size) {
    const float* nf     = (const float*)d_in[0];
    const float* chem   = (const float*)d_in[1];
    const int*   mask   = (const int*)d_in[2];     // bool stored as int32
    const float* W_node = (const float*)d_in[3];
    const float* b_node = (const float*)d_in[4];
    const float* W_edge = (const float*)d_in[5];
    const float* b_edge = (const float*)d_in[6];
    const float* W1     = (const float*)d_in[7];
    const float* b1     = (const float*)d_in[8];
    const float* W2     = (const float*)d_in[9];
    const float* b2     = (const float*)d_in[10];
    const float* W3     = (const float*)d_in[11];
    const float* b3     = (const float*)d_in[12];
    float* out = (float*)d_out;

    cudaFuncSetAttribute(sparsity_main_kernel,
                         cudaFuncAttributeMaxDynamicSharedMemorySize, SM_TOTAL);

    const int prep_blocks = PREP_NPROJ_BLK0 + (BB * NN) / PREP_ROWS;   // 25 + 128
    prep_kernel<<<prep_blocks, 256>>>(nf, W_node, b_node, W_edge, b_edge,
                                      W1, b1, W2, W3);

    dim3 grid(NN, BB);
    sparsity_main_kernel<<<grid, 256, SM_TOTAL>>>(chem, mask, b2, b3, out);
}